// round 1
// baseline (speedup 1.0000x reference)
#include <cuda_runtime.h>

#define Bv 16
#define Cv 64
#define Hv 128
#define Wv 128
#define HCv 64
#define Mv 256   // 4*Hc
#define Kv 192   // C*3

// Scratch: activated gates, layout [b][h][w][m], m = q*64 + hc
__device__ float g_gates[(size_t)Bv * Hv * Wv * Mv];

__device__ __forceinline__ void ffma2(unsigned long long& d,
                                      unsigned long long a,
                                      unsigned long long b) {
    asm("fma.rn.f32x2 %0, %1, %2, %0;" : "+l"(d) : "l"(a), "l"(b));
}

__device__ __forceinline__ float2 unpack2(unsigned long long v) {
    float2 r;
    r.x = __uint_as_float((unsigned)(v & 0xffffffffull));
    r.y = __uint_as_float((unsigned)(v >> 32));
    return r;
}

__device__ __forceinline__ float fast_sigmoid(float v) {
    // safe for all v: clamp so exp stays finite
    float e = __expf(-fmaxf(v, -30.0f));
    return __fdividef(1.0f, 1.0f + e);
}

__device__ __forceinline__ float fast_tanh(float v) {
    // e = exp(-2|v|) in (0,1] always finite
    float e = __expf(-2.0f * fabsf(v));
    float t = __fdividef(1.0f - e, 1.0f + e);
    return (v < 0.0f) ? -t : t;
}

// ---------------------------------------------------------------------------
// Kernel 1: conv(3,1 causal in H) as GEMM + bias + activations
// One block per (b,h): M=256 x N=128(W) x K=192, 512 threads.
// Thread tile: 8(M, as 4 f32x2 pairs) x 8(N).
// ---------------------------------------------------------------------------
__global__ void __launch_bounds__(512, 1)
conv_gates_kernel(const float* __restrict__ x,
                  const float* __restrict__ wgt,
                  const float* __restrict__ bias) {
    const int bh = blockIdx.x;        // b*H + h
    const int b  = bh >> 7;
    const int h  = bh & 127;

    __shared__ float  w_s[16][Mv];        // [kk][m]    16 KB
    __shared__ float2 x_s[16][Wv];        // [kk][w] duplicated (v,v)  16 KB

    const int tid = threadIdx.x;
    const int tm  = tid & 31;             // lane: m-tile index
    const int tn  = tid >> 5;             // warp: n-tile index
    const int m0  = tm * 8;
    const int n0  = tn * 8;

    unsigned long long acc[4][8];
#pragma unroll
    for (int p = 0; p < 4; p++)
#pragma unroll
        for (int j = 0; j < 8; j++) acc[p][j] = 0ull;

    // X tile loader indices (16 rows x 128 cols, float4 per thread)
    const int xr   = tid >> 5;            // 0..15 row within chunk
    const int xc   = (tid & 31) * 4;      // column (w)

    // W tile loader: p0 = tid*8 -> m = p0/16, kk0 = p0%16 (0 or 8)
    const int wm   = tid >> 1;            // p0/16 = tid*8/16
    const int wkk  = (tid & 1) * 8;

    for (int kc = 0; kc < 12; kc++) {
        const int k0 = kc * 16;

        // ---- load W tile: w_s[kk][m] = wgt[m*192 + k0 + kk]
        {
            const float4* src =
                reinterpret_cast<const float4*>(wgt + wm * Kv + k0 + wkk);
            float4 v0 = src[0];
            float4 v1 = src[1];
            w_s[wkk + 0][wm] = v0.x; w_s[wkk + 1][wm] = v0.y;
            w_s[wkk + 2][wm] = v0.z; w_s[wkk + 3][wm] = v0.w;
            w_s[wkk + 4][wm] = v1.x; w_s[wkk + 5][wm] = v1.y;
            w_s[wkk + 6][wm] = v1.z; w_s[wkk + 7][wm] = v1.w;
        }

        // ---- load X tile: row k = k0+xr -> ic = k/3, kh = k%3, h' = h+kh-2
        {
            const int k  = k0 + xr;
            const int ic = k / 3;
            const int kh = k - ic * 3;
            const int hp = h + kh - 2;
            float4 v = make_float4(0.f, 0.f, 0.f, 0.f);
            if (hp >= 0) {
                v = *reinterpret_cast<const float4*>(
                    x + ((size_t)(b * Cv + ic) * Hv + hp) * Wv + xc);
            }
            x_s[xr][xc + 0] = make_float2(v.x, v.x);
            x_s[xr][xc + 1] = make_float2(v.y, v.y);
            x_s[xr][xc + 2] = make_float2(v.z, v.z);
            x_s[xr][xc + 3] = make_float2(v.w, v.w);
        }

        __syncthreads();

#pragma unroll
        for (int kk = 0; kk < 16; kk++) {
            // a-frag: 8 consecutive m as 4 packed f32x2
            const unsigned long long* ap =
                reinterpret_cast<const unsigned long long*>(&w_s[kk][m0]);
            unsigned long long a0 = ap[0], a1 = ap[1], a2 = ap[2], a3 = ap[3];
            // b-frag: 8 duplicated x values (broadcast within warp)
            unsigned long long bb[8];
#pragma unroll
            for (int j = 0; j < 8; j++)
                bb[j] = *reinterpret_cast<const unsigned long long*>(
                    &x_s[kk][n0 + j]);
#pragma unroll
            for (int j = 0; j < 8; j++) {
                ffma2(acc[0][j], a0, bb[j]);
                ffma2(acc[1][j], a1, bb[j]);
                ffma2(acc[2][j], a2, bb[j]);
                ffma2(acc[3][j], a3, bb[j]);
            }
        }
        __syncthreads();
    }

    // ---- epilogue: bias + activation + store to g_gates[bh][w][m]
    float bias_r[8];
#pragma unroll
    for (int p = 0; p < 8; p++) bias_r[p] = bias[m0 + p];

    const bool is_g = (m0 >= 192);   // q==3 -> tanh, else sigmoid (uniform per thread)
    float* gbase = g_gates + (size_t)bh * Wv * Mv + m0;

#pragma unroll
    for (int j = 0; j < 8; j++) {
        const int w = n0 + j;
        float buf[8];
#pragma unroll
        for (int p = 0; p < 4; p++) {
            float2 v = unpack2(acc[p][j]);
            buf[2 * p + 0] = v.x + bias_r[2 * p + 0];
            buf[2 * p + 1] = v.y + bias_r[2 * p + 1];
        }
#pragma unroll
        for (int t = 0; t < 8; t++)
            buf[t] = is_g ? fast_tanh(buf[t]) : fast_sigmoid(buf[t]);

        float* dst = gbase + (size_t)w * Mv;
        *reinterpret_cast<float4*>(dst)     = make_float4(buf[0], buf[1], buf[2], buf[3]);
        *reinterpret_cast<float4*>(dst + 4) = make_float4(buf[4], buf[5], buf[6], buf[7]);
    }
}

// ---------------------------------------------------------------------------
// Kernel 2: LSTM scan over W. One block per (b,h), 64 threads (lane = hc).
// Gates layout [bh][w][q*64+hc] -> coalesced loads. Output transposed via smem.
// ---------------------------------------------------------------------------
__global__ void __launch_bounds__(64)
lstm_scan_kernel(float* __restrict__ out) {
    const int bh = blockIdx.x;
    const int b  = bh >> 7;
    const int h  = bh & 127;
    const int hc = threadIdx.x;

    __shared__ float hs[Wv][HCv + 1];   // +1 pad: conflict-free column reads

    const float* gp = g_gates + (size_t)bh * Wv * Mv + hc;
    float c = 0.0f;
#pragma unroll 4
    for (int w = 0; w < Wv; w++) {
        float iv = gp[0];
        float fv = gp[64];
        float ov = gp[128];
        float gv = gp[192];
        gp += Mv;
        c = fv * c + iv * gv;
        hs[w][hc] = ov * fast_tanh(c);
    }
    __syncthreads();

    // out[((b*HC + hc2)*H + h)*W + w] ; 64 threads sweep w, rows over hc2
#pragma unroll 1
    for (int hc2 = 0; hc2 < HCv; hc2++) {
        float* orow = out + ((size_t)(b * HCv + hc2) * Hv + h) * Wv;
        orow[hc]      = hs[hc][hc2];
        orow[hc + 64] = hs[hc + 64][hc2];
    }
}

extern "C" void kernel_launch(void* const* d_in, const int* in_sizes, int n_in,
                              void* d_out, int out_size) {
    const float* x    = (const float*)d_in[0];
    const float* wgt  = (const float*)d_in[1];
    const float* bias = (const float*)d_in[2];
    float* out = (float*)d_out;

    conv_gates_kernel<<<Bv * Hv, 512>>>(x, wgt, bias);
    lstm_scan_kernel<<<Bv * Hv, 64>>>(out);
}

// round 3
// speedup vs baseline: 2.2380x; 2.2380x over previous
#include <cuda_runtime.h>
#include <cuda_bf16.h>
#include <cstdint>

#define Bv 16
#define Cv 64
#define Hv 128
#define Wv 128
#define HCv 64
#define Mv 256   // 4*Hc
#define Kv 192   // C*3

// W image: [chunk(3)][plane(2: hi,lo)][m(256)][36 words], exact smem layout
__device__ uint32_t g_wimg[3 * 2 * 256 * 36];

// ---- smem word-offset map (one extern buffer, stage region aliased by gates)
#define WLO_W   9216     // wlo plane base (whi at 0)
#define XHI_W   18432
#define XLO_W   23040    // XHI + 4608
#define GSTRIDE 260      // gates row stride in words: [w][260]
#define PS_W    33280    // 4 segs * 64 hc * 2 floats
#define SMEM_BYTES 135168

extern __shared__ uint32_t smw[];

__device__ __forceinline__ float fast_sigmoid(float v) {
    float e = __expf(-v);
    return __fdividef(1.0f, 1.0f + e);
}
__device__ __forceinline__ float fast_tanh(float v) {
    float e = __expf(-2.0f * fabsf(v));
    float t = __fdividef(1.0f - e, 1.0f + e);
    return (v < 0.0f) ? -t : t;
}

__device__ __forceinline__ void mma_bf16(float* c, const uint32_t* a,
                                         uint32_t b0, uint32_t b1) {
    asm volatile(
        "mma.sync.aligned.m16n8k16.row.col.f32.bf16.bf16.f32 "
        "{%0,%1,%2,%3}, {%4,%5,%6,%7}, {%8,%9}, {%0,%1,%2,%3};\n"
        : "+f"(c[0]), "+f"(c[1]), "+f"(c[2]), "+f"(c[3])
        : "r"(a[0]), "r"(a[1]), "r"(a[2]), "r"(a[3]), "r"(b0), "r"(b1));
}

__device__ __forceinline__ void split_pack(float v0, float v1,
                                           uint32_t& hi, uint32_t& lo) {
    __nv_bfloat16 h0 = __float2bfloat16(v0);
    __nv_bfloat16 h1 = __float2bfloat16(v1);
    float l0f = v0 - __bfloat162float(h0);
    float l1f = v1 - __bfloat162float(h1);
    __nv_bfloat16 l0 = __float2bfloat16(l0f);
    __nv_bfloat16 l1 = __float2bfloat16(l1f);
    hi = ((uint32_t)__bfloat16_as_ushort(h1) << 16) | __bfloat16_as_ushort(h0);
    lo = ((uint32_t)__bfloat16_as_ushort(l1) << 16) | __bfloat16_as_ushort(l0);
}

// ---------------------------------------------------------------- prep W image
// k = ic*3 + kh ; word kw packs k-pair (2kw, 2kw+1). Row offset swizzle: +((m>>3)&3)
__global__ void prep_w(const float* __restrict__ wgt) {
    int kwg = blockIdx.x;           // chunk*32 + kw
    int m = threadIdx.x;
    int chunk = kwg >> 5, kw = kwg & 31;
    int k0 = chunk * 64 + kw * 2;
    float v0 = wgt[m * Kv + k0];
    float v1 = wgt[m * Kv + k0 + 1];
    uint32_t hi, lo;
    split_pack(v0, v1, hi, lo);
    int off = kw + ((m >> 3) & 3);
    g_wimg[((chunk * 2 + 0) * 256 + m) * 36 + off] = hi;
    g_wimg[((chunk * 2 + 1) * 256 + m) * 36 + off] = lo;
}

// ---------------------------------------------------------------- fused kernel
// One block per (b,h). GEMM D[256m x 128w] = W[m,k] X[k,w], K=192 in 3 chunks of 64.
// 8 warps = 4(m) x 2(n); warp tile 64x64; mma.sync m16n8k16 bf16, 3-term split.
// Then: bias+activation -> gates smem [w][260] -> 4-segment parallel LSTM scan -> out.
__global__ void __launch_bounds__(256, 1)
rowlstm_fused(const float* __restrict__ x, const float* __restrict__ bias,
              float* __restrict__ out) {
    float* smf = reinterpret_cast<float*>(smw);
    const int tid = threadIdx.x;
    const int wid = tid >> 5;
    const int lane = tid & 31;
    const int mw = wid & 3;          // m warp coord (also gate index q!)
    const int nw = wid >> 2;         // n warp coord
    const int r = lane >> 2;
    const int cl = lane & 3;

    const int bh = blockIdx.x;
    const int b = bh >> 7;
    const int h = bh & 127;

    // frag base word offsets
    int aw0[4], aw1[4];
#pragma unroll
    for (int mt = 0; mt < 4; mt++) {
        int m0 = mw * 64 + mt * 16;
        int ra = m0 + r, rb = m0 + 8 + r;
        aw0[mt] = ra * 36 + ((ra >> 3) & 3) + cl;
        aw1[mt] = rb * 36 + ((rb >> 3) & 3) + cl;
    }
    int bw[8];
#pragma unroll
    for (int nt = 0; nt < 8; nt++) {
        int nr = nw * 64 + nt * 8 + r;
        bw[nt] = XHI_W + nr * 36 + ((nr >> 3) & 3) + cl;
    }

    // bias for this thread's m rows
    float bias_lo[4], bias_hi[4];
#pragma unroll
    for (int mt = 0; mt < 4; mt++) {
        int m0 = mw * 64 + mt * 16;
        bias_lo[mt] = bias[m0 + r];
        bias_hi[mt] = bias[m0 + 8 + r];
    }

    float acc[4][8][4];
#pragma unroll
    for (int mt = 0; mt < 4; mt++)
#pragma unroll
        for (int nt = 0; nt < 8; nt++)
#pragma unroll
            for (int q = 0; q < 4; q++) acc[mt][nt][q] = 0.0f;

    // X staging mapping: n = tid&127, kw half = (tid>>7)*16
    const int xn = tid & 127;
    const int kh16 = (tid >> 7) * 16;
    const int xoff = xn * 36 + ((xn >> 3) & 3);

    for (int chunk = 0; chunk < 3; chunk++) {
        // ---- stage W: linear copy 18432 words (both planes)
        {
            const uint4* src = reinterpret_cast<const uint4*>(g_wimg) + chunk * 4608;
            uint4* dst = reinterpret_cast<uint4*>(smw);
#pragma unroll
            for (int j = 0; j < 18; j++) dst[tid + j * 256] = src[tid + j * 256];
        }
        // ---- stage X: 16 k-words per thread, split to bf16 hi/lo
#pragma unroll 4
        for (int j = 0; j < 16; j++) {
            int kw = kh16 + j;
            int kg = chunk * 64 + kw * 2;
            int ic0 = kg / 3, r0 = kg - ic0 * 3;
            int kg1 = kg + 1;
            int ic1 = kg1 / 3, r1 = kg1 - ic1 * 3;
            int hp0 = h + r0 - 2, hp1 = h + r1 - 2;
            float v0 = (hp0 >= 0) ? x[((b * Cv + ic0) * Hv + hp0) * Wv + xn] : 0.0f;
            float v1 = (hp1 >= 0) ? x[((b * Cv + ic1) * Hv + hp1) * Wv + xn] : 0.0f;
            uint32_t hi, lo;
            split_pack(v0, v1, hi, lo);
            smw[XHI_W + xoff + kw] = hi;
            smw[XLO_W + xoff + kw] = lo;
        }
        __syncthreads();

        // ---- mainloop: 4 ksteps of k16
#pragma unroll
        for (int ks = 0; ks < 4; ks++) {
            const int wb = ks * 8;
            uint32_t Ah[4][4], Al[4][4];
#pragma unroll
            for (int mt = 0; mt < 4; mt++) {
                Ah[mt][0] = smw[aw0[mt] + wb];
                Ah[mt][1] = smw[aw1[mt] + wb];
                Ah[mt][2] = smw[aw0[mt] + wb + 4];
                Ah[mt][3] = smw[aw1[mt] + wb + 4];
                Al[mt][0] = smw[aw0[mt] + wb + WLO_W];
                Al[mt][1] = smw[aw1[mt] + wb + WLO_W];
                Al[mt][2] = smw[aw0[mt] + wb + 4 + WLO_W];
                Al[mt][3] = smw[aw1[mt] + wb + 4 + WLO_W];
            }
#pragma unroll
            for (int nt = 0; nt < 8; nt++) {
                uint32_t bh0 = smw[bw[nt] + wb];
                uint32_t bh1 = smw[bw[nt] + wb + 4];
                uint32_t bl0 = smw[bw[nt] + wb + 4608];
                uint32_t bl1 = smw[bw[nt] + wb + 4 + 4608];
#pragma unroll
                for (int mt = 0; mt < 4; mt++) {
                    mma_bf16(acc[mt][nt], Ah[mt], bh0, bh1);   // hi*hi
                    mma_bf16(acc[mt][nt], Ah[mt], bl0, bl1);   // hi*lo
                    mma_bf16(acc[mt][nt], Al[mt], bh0, bh1);   // lo*hi
                }
            }
        }
        __syncthreads();   // stage buffer reusable / gates alias safe
    }

    // ---- epilogue: bias + activation -> gates smem [w][260]
    const bool isg = (mw == 3);   // q = mw
#pragma unroll
    for (int mt = 0; mt < 4; mt++) {
        const int m0 = mw * 64 + mt * 16;
#pragma unroll
        for (int nt = 0; nt < 8; nt++) {
            const int w0 = nw * 64 + nt * 8 + 2 * cl;
            float v0 = acc[mt][nt][0] + bias_lo[mt];
            float v1 = acc[mt][nt][1] + bias_lo[mt];
            float v2 = acc[mt][nt][2] + bias_hi[mt];
            float v3 = acc[mt][nt][3] + bias_hi[mt];
            if (isg) {
                v0 = fast_tanh(v0); v1 = fast_tanh(v1);
                v2 = fast_tanh(v2); v3 = fast_tanh(v3);
            } else {
                v0 = fast_sigmoid(v0); v1 = fast_sigmoid(v1);
                v2 = fast_sigmoid(v2); v3 = fast_sigmoid(v3);
            }
            smf[(size_t)w0 * GSTRIDE + m0 + r]           = v0;
            smf[(size_t)(w0 + 1) * GSTRIDE + m0 + r]     = v1;
            smf[(size_t)w0 * GSTRIDE + m0 + 8 + r]       = v2;
            smf[(size_t)(w0 + 1) * GSTRIDE + m0 + 8 + r] = v3;
        }
    }
    __syncthreads();

    // ---- LSTM scan: 4 segments of 32 w, parallel linear recurrence
    const int seg = tid >> 6;
    const int hc = tid & 63;

    // pass 1: segment-local c (c_in=0) and running f-product; stash per-step
    {
        int gb = seg * 32 * GSTRIDE + hc;
        float c = 0.0f, P = 1.0f;
#pragma unroll 8
        for (int j = 0; j < 32; j++) {
            float iv = smf[gb];
            float fv = smf[gb + 64];
            float gv = smf[gb + 192];
            c = fmaf(fv, c, iv * gv);
            P *= fv;
            smf[gb + 64] = c;    // c_partial over f-slot
            smf[gb + 192] = P;   // f-prod over g-slot
            gb += GSTRIDE;
        }
        smf[PS_W + (seg * 64 + hc) * 2] = P;
        smf[PS_W + (seg * 64 + hc) * 2 + 1] = c;
    }
    __syncthreads();

    // pass 2: incoming c for this segment
    float cin = 0.0f;
#pragma unroll
    for (int s2 = 0; s2 < 3; s2++) {
        if (s2 < seg) {
            float P = smf[PS_W + (s2 * 64 + hc) * 2];
            float S = smf[PS_W + (s2 * 64 + hc) * 2 + 1];
            cin = fmaf(P, cin, S);
        }
    }

    // pass 3: true c, h = o*tanh(c), write out (w-contiguous per thread)
    {
        int gb = seg * 32 * GSTRIDE + hc;
        float4* po = reinterpret_cast<float4*>(
            out + ((size_t)(b * HCv + hc) * Hv + h) * Wv + seg * 32);
        float hb[4];
#pragma unroll 8
        for (int j = 0; j < 32; j++) {
            float cp = smf[gb + 64];
            float fp = smf[gb + 192];
            float ov = smf[gb + 128];
            float cc = fmaf(fp, cin, cp);
            hb[j & 3] = ov * fast_tanh(cc);
            if ((j & 3) == 3)
                po[j >> 2] = make_float4(hb[0], hb[1], hb[2], hb[3]);
            gb += GSTRIDE;
        }
    }
}

extern "C" void kernel_launch(void* const* d_in, const int* in_sizes, int n_in,
                              void* d_out, int out_size) {
    const float* x    = (const float*)d_in[0];
    const float* wgt  = (const float*)d_in[1];
    const float* bias = (const float*)d_in[2];
    float* out = (float*)d_out;

    cudaFuncSetAttribute(rowlstm_fused,
                         cudaFuncAttributeMaxDynamicSharedMemorySize, SMEM_BYTES);

    prep_w<<<96, 256>>>(wgt);
    rowlstm_fused<<<Bv * Hv, 256, SMEM_BYTES>>>(x, bias, out);
}

// round 4
// speedup vs baseline: 2.8921x; 1.2923x over previous
#include <cuda_runtime.h>
#include <cuda_bf16.h>
#include <cstdint>

#define Bv 16
#define Cv 64
#define Hv 128
#define Wv 128
#define HCv 64

// Pre-baked W image: [chunk(3)][plane(2)][m(256)][k(64) octet-swizzled] bf16
__device__ __align__(16) uint16_t g_wimg[3 * 2 * 256 * 64];

// ---- smem map (bytes) ----
// stage:  WBUF (2 bufs x 64KB) at 0 ; XBUF (2 bufs x 32KB) at 131072  -> 196608
// after mainloop (aliased): gates [w(128)][260 words] + PS at word 33280
#define XBUF_B   131072
#define GST      260
#define PS_W     33280
#define SMEM_BYTES 196608

extern __shared__ uint32_t smw[];

__device__ __forceinline__ uint32_t smem_u32(const void* p) {
    uint32_t a;
    asm("{ .reg .u64 t; cvta.to.shared.u64 t, %1; cvt.u32.u64 %0, t; }"
        : "=r"(a) : "l"(p));
    return a;
}

__device__ __forceinline__ float fast_sigmoid(float v) {
    float e = __expf(-v);
    return __fdividef(1.0f, 1.0f + e);
}
__device__ __forceinline__ float fast_tanh(float v) {
    float e = __expf(-2.0f * fabsf(v));
    float t = __fdividef(1.0f - e, 1.0f + e);
    return (v < 0.0f) ? -t : t;
}

__device__ __forceinline__ void mma_bf16(float* c, const uint32_t* a,
                                         uint32_t b0, uint32_t b1) {
    asm volatile(
        "mma.sync.aligned.m16n8k16.row.col.f32.bf16.bf16.f32 "
        "{%0,%1,%2,%3}, {%4,%5,%6,%7}, {%8,%9}, {%0,%1,%2,%3};\n"
        : "+f"(c[0]), "+f"(c[1]), "+f"(c[2]), "+f"(c[3])
        : "r"(a[0]), "r"(a[1]), "r"(a[2]), "r"(a[3]), "r"(b0), "r"(b1));
}

#define LDM4(R, addr) \
    asm volatile("ldmatrix.sync.aligned.m8n8.x4.shared.b16 {%0,%1,%2,%3}, [%4];" \
        : "=r"((R)[0]), "=r"((R)[1]), "=r"((R)[2]), "=r"((R)[3]) : "r"(addr))
#define LDM4T(R, addr) \
    asm volatile("ldmatrix.sync.aligned.m8n8.x4.trans.shared.b16 {%0,%1,%2,%3}, [%4];" \
        : "=r"((R)[0]), "=r"((R)[1]), "=r"((R)[2]), "=r"((R)[3]) : "r"(addr))
#define CPA16(dst, src) \
    asm volatile("cp.async.ca.shared.global [%0], [%1], 16;" :: "r"(dst), "l"(src))
#define CPA_COMMIT() asm volatile("cp.async.commit_group;" ::: "memory")
#define CPA_WAIT0()  asm volatile("cp.async.wait_group 0;" ::: "memory")

__device__ __forceinline__ void split_pack(float v0, float v1,
                                           uint32_t& hi, uint32_t& lo) {
    __nv_bfloat16 h0 = __float2bfloat16(v0);
    __nv_bfloat16 h1 = __float2bfloat16(v1);
    __nv_bfloat16 l0 = __float2bfloat16(v0 - __bfloat162float(h0));
    __nv_bfloat16 l1 = __float2bfloat16(v1 - __bfloat162float(h1));
    hi = ((uint32_t)__bfloat16_as_ushort(h1) << 16) | __bfloat16_as_ushort(h0);
    lo = ((uint32_t)__bfloat16_as_ushort(l1) << 16) | __bfloat16_as_ushort(l0);
}

// ---------------------------------------------------------------- prep W image
// grid 192 (k), block 256 (m). Bakes bf16 hi/lo with octet swizzle o^(m&7).
__global__ void prep_w(const float* __restrict__ wgt) {
    int k = blockIdx.x;
    int m = threadIdx.x;
    float v = wgt[m * 192 + k];
    __nv_bfloat16 hb = __float2bfloat16(v);
    __nv_bfloat16 lb = __float2bfloat16(v - __bfloat162float(hb));
    int c = k >> 6, kl = k & 63, o = kl >> 3, e = kl & 7;
    int base = c * 32768 + m * 64 + (((o ^ (m & 7)) << 3) + e);  // uint16 units
    g_wimg[base] = __bfloat16_as_ushort(hb);
    g_wimg[base + 16384] = __bfloat16_as_ushort(lb);
}

// ---------------------------------------------------------------- fused kernel
// One block per (b,h), 512 threads = 16 warps (4m x 4n), warp tile 64x32.
// 3 K-chunks of 64; cp.async double-buffered W, reg-prefetched X.
__global__ void __launch_bounds__(512, 1)
rowlstm_fused(const float* __restrict__ x, const float* __restrict__ bias,
              float* __restrict__ out) {
    float* smf = reinterpret_cast<float*>(smw);
    const int tid = threadIdx.x;
    const int lane = tid & 31;
    const int wid = tid >> 5;
    const int mw = wid & 3;
    const int nw = wid >> 2;
    const int r = lane >> 2, cl = lane & 3;
    const int bh = blockIdx.x, b = bh >> 7, h = bh & 127;

    const uint32_t smb = smem_u32(smw);

    // staging mapping
    const int woct = tid & 15;
    const int krbase = tid >> 4;   // 0..31

    // ldmatrix lane params
    const int l7 = lane & 7, l15 = lane & 15, lk = lane >> 4;
    const int krl = l7 + ((lane & 16) >> 1);
    const int wo = (lane >> 3) & 1;

    uint64_t gw;
    {
        const char* p = reinterpret_cast<const char*>(g_wimg);
        asm("cvta.to.global.u64 %0, %1;" : "=l"(gw) : "l"(p));
    }

    float acc[4][4][4];
#pragma unroll
    for (int mt = 0; mt < 4; mt++)
#pragma unroll
        for (int nt = 0; nt < 4; nt++)
#pragma unroll
            for (int q = 0; q < 4; q++) acc[mt][nt][q] = 0.0f;

    float4 pva[2], pvb[2];

#define LOAD_X(cn)                                                          \
    do {                                                                    \
        _Pragma("unroll") for (int j = 0; j < 2; j++) {                     \
            int krow = krbase + j * 32;                                     \
            int kg = (cn) * 64 + krow;                                      \
            int ic = kg / 3;                                                \
            int kh = kg - 3 * ic;                                           \
            int hp = h + kh - 2;                                            \
            if (hp >= 0) {                                                  \
                const float4* p4 = reinterpret_cast<const float4*>(         \
                    x + ((size_t)((b * Cv + ic) * Hv + hp)) * Wv + woct * 8); \
                pva[j] = p4[0];                                             \
                pvb[j] = p4[1];                                             \
            } else {                                                        \
                pva[j] = make_float4(0.f, 0.f, 0.f, 0.f);                   \
                pvb[j] = pva[j];                                            \
            }                                                               \
        }                                                                   \
    } while (0)

#define STS_X(db)                                                           \
    do {                                                                    \
        _Pragma("unroll") for (int j = 0; j < 2; j++) {                     \
            int krow = krbase + j * 32;                                     \
            uint32_t hiw[4], low[4];                                        \
            split_pack(pva[j].x, pva[j].y, hiw[0], low[0]);                 \
            split_pack(pva[j].z, pva[j].w, hiw[1], low[1]);                 \
            split_pack(pvb[j].x, pvb[j].y, hiw[2], low[2]);                 \
            split_pack(pvb[j].z, pvb[j].w, hiw[3], low[3]);                 \
            uint32_t a0 = smb + XBUF_B + (db) * 32768 + krow * 256 +        \
                          ((woct ^ (krow & 7)) << 4);                       \
            asm volatile("st.shared.v4.b32 [%0], {%1,%2,%3,%4};"            \
                         :: "r"(a0), "r"(hiw[0]), "r"(hiw[1]), "r"(hiw[2]), \
                            "r"(hiw[3]) : "memory");                        \
            asm volatile("st.shared.v4.b32 [%0], {%1,%2,%3,%4};"            \
                         :: "r"(a0 + 16384), "r"(low[0]), "r"(low[1]),      \
                            "r"(low[2]), "r"(low[3]) : "memory");           \
        }                                                                   \
    } while (0)

#define CP_W(cn, db)                                                        \
    do {                                                                    \
        uint64_t src = gw + (uint64_t)(cn) * 65536 + tid * 16;              \
        uint32_t dst = smb + (db) * 65536 + tid * 16;                       \
        _Pragma("unroll") for (int j = 0; j < 8; j++)                       \
            CPA16(dst + j * 8192, src + j * 8192);                          \
        CPA_COMMIT();                                                       \
    } while (0)

    // ---- preamble: stage chunk 0
    LOAD_X(0);
    CP_W(0, 0);
    STS_X(0);
    CPA_WAIT0();
    __syncthreads();

#pragma unroll
    for (int c = 0; c < 3; c++) {
        const int db = c & 1;
        if (c < 2) {
            LOAD_X(c + 1);       // LDGs in flight under the MMAs
            CP_W(c + 1, db ^ 1); // async W copy under the MMAs
        }

        // ---- mainloop: 4 ksteps over this 64-k chunk
        const uint32_t a_h = smb + db * 65536 + (mw * 64 + l15) * 128;
        const uint32_t a_l = a_h + 32768;
        uint32_t bb[2];
#pragma unroll
        for (int np = 0; np < 2; np++) {
            int oct = ((nw * 32 + np * 16) >> 3) + wo;
            bb[np] = smb + XBUF_B + db * 32768 + krl * 256 + ((oct ^ l7) << 4);
        }
#pragma unroll
        for (int ks = 0; ks < 4; ks++) {
            uint32_t Bh[2][4], Bl[2][4];
#pragma unroll
            for (int np = 0; np < 2; np++) {
                LDM4T(Bh[np], bb[np] + ks * 4096);
                LDM4T(Bl[np], bb[np] + ks * 4096 + 16384);
            }
            const uint32_t swA = (uint32_t)(((2 * ks + lk) ^ l7) << 4);
#pragma unroll
            for (int mt = 0; mt < 4; mt++) {
                uint32_t Ah[4], Al[4];
                LDM4(Ah, a_h + mt * 2048 + swA);
                LDM4(Al, a_l + mt * 2048 + swA);
#pragma unroll
                for (int nt = 0; nt < 4; nt++) {
                    const int np = nt >> 1, ix = nt & 1;
                    mma_bf16(acc[mt][nt], Ah, Bh[np][ix], Bh[np][2 + ix]);
                    mma_bf16(acc[mt][nt], Ah, Bl[np][ix], Bl[np][2 + ix]);
                    mma_bf16(acc[mt][nt], Al, Bh[np][ix], Bh[np][2 + ix]);
                }
            }
        }

        if (c < 2) {
            STS_X(db ^ 1);
            CPA_WAIT0();
            __syncthreads();
        }
    }
    __syncthreads();  // all warps done reading stage buffers (gates alias them)

    // ---- epilogue: bias + activation -> gates smem [w][260]
    const bool isg = (mw == 3);
#pragma unroll
    for (int mt = 0; mt < 4; mt++) {
        const int m0 = mw * 64 + mt * 16;
        const float blo = bias[m0 + r];
        const float bhi = bias[m0 + 8 + r];
#pragma unroll
        for (int nt = 0; nt < 4; nt++) {
            const int w0 = nw * 32 + nt * 8 + 2 * cl;
            float v0 = acc[mt][nt][0] + blo;
            float v1 = acc[mt][nt][1] + blo;
            float v2 = acc[mt][nt][2] + bhi;
            float v3 = acc[mt][nt][3] + bhi;
            if (isg) {
                v0 = fast_tanh(v0); v1 = fast_tanh(v1);
                v2 = fast_tanh(v2); v3 = fast_tanh(v3);
            } else {
                v0 = fast_sigmoid(v0); v1 = fast_sigmoid(v1);
                v2 = fast_sigmoid(v2); v3 = fast_sigmoid(v3);
            }
            smf[(size_t)w0 * GST + m0 + r]           = v0;
            smf[(size_t)(w0 + 1) * GST + m0 + r]     = v1;
            smf[(size_t)w0 * GST + m0 + 8 + r]       = v2;
            smf[(size_t)(w0 + 1) * GST + m0 + 8 + r] = v3;
        }
    }
    __syncthreads();

    // ---- LSTM scan: 8 segments of 16 w, parallel linear recurrence
    const int seg = tid >> 6;
    const int hc = tid & 63;
    {
        int gb = seg * 16 * GST + hc;
        float c = 0.0f, P = 1.0f;
#pragma unroll 8
        for (int j = 0; j < 16; j++) {
            float iv = smf[gb];
            float fv = smf[gb + 64];
            float gv = smf[gb + 192];
            c = fmaf(fv, c, iv * gv);
            P *= fv;
            smf[gb + 64] = c;
            smf[gb + 192] = P;
            gb += GST;
        }
        smf[PS_W + (seg * 64 + hc) * 2] = P;
        smf[PS_W + (seg * 64 + hc) * 2 + 1] = c;
    }
    __syncthreads();

    float cin = 0.0f;
#pragma unroll
    for (int s2 = 0; s2 < 7; s2++) {
        if (s2 < seg) {
            float P = smf[PS_W + (s2 * 64 + hc) * 2];
            float S = smf[PS_W + (s2 * 64 + hc) * 2 + 1];
            cin = fmaf(P, cin, S);
        }
    }

    {
        int gb = seg * 16 * GST + hc;
        float4* po = reinterpret_cast<float4*>(
            out + ((size_t)(b * HCv + hc) * Hv + h) * Wv + seg * 16);
        float hb[4];
#pragma unroll 4
        for (int j = 0; j < 16; j++) {
            float cp = smf[gb + 64];
            float fp = smf[gb + 192];
            float ov = smf[gb + 128];
            float cc = fmaf(fp, cin, cp);
            hb[j & 3] = ov * fast_tanh(cc);
            if ((j & 3) == 3)
                po[j >> 2] = make_float4(hb[0], hb[1], hb[2], hb[3]);
            gb += GST;
        }
    }
}

extern "C" void kernel_launch(void* const* d_in, const int* in_sizes, int n_in,
                              void* d_out, int out_size) {
    const float* x    = (const float*)d_in[0];
    const float* wgt  = (const float*)d_in[1];
    const float* bias = (const float*)d_in[2];
    float* out = (float*)d_out;

    cudaFuncSetAttribute(rowlstm_fused,
                         cudaFuncAttributeMaxDynamicSharedMemorySize, SMEM_BYTES);

    prep_w<<<192, 256>>>(wgt);
    rowlstm_fused<<<Bv * Hv, 512, SMEM_BYTES>>>(x, bias, out);
}

// round 5
// speedup vs baseline: 2.9074x; 1.0053x over previous
#include <cuda_runtime.h>
#include <cuda_bf16.h>
#include <cstdint>

#define Bv 16
#define Cv 64
#define Hv 128
#define Wv 128
#define HCv 64

// Pre-baked W image: [chunk(3)][plane(2)][m(256)][k(64) octet-swizzled] bf16
__device__ __align__(16) uint16_t g_wimg[3 * 2 * 256 * 64];

// ---- smem map (bytes) ----
// stage:  WBUF (2 bufs x 64KB) at 0 ; XBUF (2 bufs x 32KB) at 131072  -> 196608
// after mainloop (aliased): gates [w(128)][260 words] + PS at word 33280
#define XBUF_B   131072
#define GST      260
#define PS_W     33280
#define SMEM_BYTES 196608

extern __shared__ uint32_t smw[];

__device__ __forceinline__ uint32_t smem_u32(const void* p) {
    uint32_t a;
    asm("{ .reg .u64 t; cvta.to.shared.u64 t, %1; cvt.u32.u64 %0, t; }"
        : "=r"(a) : "l"(p));
    return a;
}

__device__ __forceinline__ float rcp_fast(float d) {
    float r;
    asm("rcp.approx.ftz.f32 %0, %1;" : "=f"(r) : "f"(d));
    return r;
}

// paired sigmoid: one RCP for two values
__device__ __forceinline__ void sigmoid2(float& v0, float& v1) {
    float e0 = __expf(-fmaxf(v0, -30.0f));
    float e1 = __expf(-fmaxf(v1, -30.0f));
    float p0 = 1.0f + e0, p1 = 1.0f + e1;
    float r = rcp_fast(p0 * p1);
    v0 = p1 * r;
    v1 = p0 * r;
}
// paired tanh: one RCP for two values
__device__ __forceinline__ void tanh2(float& v0, float& v1) {
    float e0 = __expf(-2.0f * fabsf(v0));
    float e1 = __expf(-2.0f * fabsf(v1));
    float p0 = 1.0f + e0, p1 = 1.0f + e1;
    float r = rcp_fast(p0 * p1);
    float t0 = (1.0f - e0) * p1 * r;
    float t1 = (1.0f - e1) * p0 * r;
    v0 = (v0 < 0.0f) ? -t0 : t0;
    v1 = (v1 < 0.0f) ? -t1 : t1;
}
__device__ __forceinline__ float fast_tanh1(float v) {
    float e = __expf(-2.0f * fabsf(v));
    float t = (1.0f - e) * rcp_fast(1.0f + e);
    return (v < 0.0f) ? -t : t;
}

__device__ __forceinline__ void mma_bf16(float* c, const uint32_t* a,
                                         uint32_t b0, uint32_t b1) {
    asm volatile(
        "mma.sync.aligned.m16n8k16.row.col.f32.bf16.bf16.f32 "
        "{%0,%1,%2,%3}, {%4,%5,%6,%7}, {%8,%9}, {%0,%1,%2,%3};\n"
        : "+f"(c[0]), "+f"(c[1]), "+f"(c[2]), "+f"(c[3])
        : "r"(a[0]), "r"(a[1]), "r"(a[2]), "r"(a[3]), "r"(b0), "r"(b1));
}

#define LDM4(R, addr) \
    asm volatile("ldmatrix.sync.aligned.m8n8.x4.shared.b16 {%0,%1,%2,%3}, [%4];" \
        : "=r"((R)[0]), "=r"((R)[1]), "=r"((R)[2]), "=r"((R)[3]) : "r"(addr))
#define LDM4T(R, addr) \
    asm volatile("ldmatrix.sync.aligned.m8n8.x4.trans.shared.b16 {%0,%1,%2,%3}, [%4];" \
        : "=r"((R)[0]), "=r"((R)[1]), "=r"((R)[2]), "=r"((R)[3]) : "r"(addr))
#define CPA16(dst, src) \
    asm volatile("cp.async.ca.shared.global [%0], [%1], 16;" :: "r"(dst), "l"(src))
#define CPA_COMMIT() asm volatile("cp.async.commit_group;" ::: "memory")
#define CPA_WAIT0()  asm volatile("cp.async.wait_group 0;" ::: "memory")

__device__ __forceinline__ void split_pack(float v0, float v1,
                                           uint32_t& hi, uint32_t& lo) {
    __nv_bfloat16 h0 = __float2bfloat16(v0);
    __nv_bfloat16 h1 = __float2bfloat16(v1);
    __nv_bfloat16 l0 = __float2bfloat16(v0 - __bfloat162float(h0));
    __nv_bfloat16 l1 = __float2bfloat16(v1 - __bfloat162float(h1));
    hi = ((uint32_t)__bfloat16_as_ushort(h1) << 16) | __bfloat16_as_ushort(h0);
    lo = ((uint32_t)__bfloat16_as_ushort(l1) << 16) | __bfloat16_as_ushort(l0);
}

// ---------------------------------------------------------------- prep W image
__global__ void prep_w(const float* __restrict__ wgt) {
    int k = blockIdx.x;
    int m = threadIdx.x;
    float v = wgt[m * 192 + k];
    __nv_bfloat16 hb = __float2bfloat16(v);
    __nv_bfloat16 lb = __float2bfloat16(v - __bfloat162float(hb));
    int c = k >> 6, kl = k & 63, o = kl >> 3, e = kl & 7;
    int base = c * 32768 + m * 64 + (((o ^ (m & 7)) << 3) + e);  // uint16 units
    g_wimg[base] = __bfloat16_as_ushort(hb);
    g_wimg[base + 16384] = __bfloat16_as_ushort(lb);
}

// ---------------------------------------------------------------- fused kernel
__global__ void __launch_bounds__(512, 1)
rowlstm_fused(const float* __restrict__ x, const float* __restrict__ bias,
              float* __restrict__ out) {
    float* smf = reinterpret_cast<float*>(smw);
    const int tid = threadIdx.x;
    const int lane = tid & 31;
    const int wid = tid >> 5;
    const int mw = wid & 3;
    const int nw = wid >> 2;
    const int r = lane >> 2, cl = lane & 3;
    const int bh = blockIdx.x, b = bh >> 7, h = bh & 127;

    const uint32_t smb = smem_u32(smw);

    // staging mapping
    const int woct = tid & 15;
    const int krbase = tid >> 4;   // 0..31

    // ldmatrix lane params
    const int l7 = lane & 7, l15 = lane & 15, lk = lane >> 4;
    const int krl = l7 + ((lane & 16) >> 1);
    const int wo = (lane >> 3) & 1;

    uint64_t gw;
    {
        const char* p = reinterpret_cast<const char*>(g_wimg);
        asm("cvta.to.global.u64 %0, %1;" : "=l"(gw) : "l"(p));
    }

    float acc[4][4][4];
#pragma unroll
    for (int mt = 0; mt < 4; mt++)
#pragma unroll
        for (int nt = 0; nt < 4; nt++)
#pragma unroll
            for (int q = 0; q < 4; q++) acc[mt][nt][q] = 0.0f;

    float4 pva[2], pvb[2];

#define LOAD_X(cn)                                                          \
    do {                                                                    \
        _Pragma("unroll") for (int j = 0; j < 2; j++) {                     \
            int krow = krbase + j * 32;                                     \
            int kg = (cn) * 64 + krow;                                      \
            int ic = kg / 3;                                                \
            int kh = kg - 3 * ic;                                           \
            int hp = h + kh - 2;                                            \
            if (hp >= 0) {                                                  \
                const float4* p4 = reinterpret_cast<const float4*>(         \
                    x + ((size_t)((b * Cv + ic) * Hv + hp)) * Wv + woct * 8); \
                pva[j] = p4[0];                                             \
                pvb[j] = p4[1];                                             \
            } else {                                                        \
                pva[j] = make_float4(0.f, 0.f, 0.f, 0.f);                   \
                pvb[j] = pva[j];                                            \
            }                                                               \
        }                                                                   \
    } while (0)

#define STS_X(db)                                                           \
    do {                                                                    \
        _Pragma("unroll") for (int j = 0; j < 2; j++) {                     \
            int krow = krbase + j * 32;                                     \
            uint32_t hiw[4], low[4];                                        \
            split_pack(pva[j].x, pva[j].y, hiw[0], low[0]);                 \
            split_pack(pva[j].z, pva[j].w, hiw[1], low[1]);                 \
            split_pack(pvb[j].x, pvb[j].y, hiw[2], low[2]);                 \
            split_pack(pvb[j].z, pvb[j].w, hiw[3], low[3]);                 \
            uint32_t a0 = smb + XBUF_B + (db) * 32768 + krow * 256 +        \
                          ((woct ^ (krow & 7)) << 4);                       \
            asm volatile("st.shared.v4.b32 [%0], {%1,%2,%3,%4};"            \
                         :: "r"(a0), "r"(hiw[0]), "r"(hiw[1]), "r"(hiw[2]), \
                            "r"(hiw[3]) : "memory");                        \
            asm volatile("st.shared.v4.b32 [%0], {%1,%2,%3,%4};"            \
                         :: "r"(a0 + 16384), "r"(low[0]), "r"(low[1]),      \
                            "r"(low[2]), "r"(low[3]) : "memory");           \
        }                                                                   \
    } while (0)

#define CP_W(cn, db)                                                        \
    do {                                                                    \
        uint64_t src = gw + (uint64_t)(cn) * 65536 + tid * 16;              \
        uint32_t dst = smb + (db) * 65536 + tid * 16;                       \
        _Pragma("unroll") for (int j = 0; j < 8; j++)                       \
            CPA16(dst + j * 8192, src + j * 8192);                          \
        CPA_COMMIT();                                                       \
    } while (0)

    // ---- preamble: stage chunk 0
    LOAD_X(0);
    CP_W(0, 0);
    STS_X(0);
    CPA_WAIT0();
    __syncthreads();

#pragma unroll
    for (int c = 0; c < 3; c++) {
        const int db = c & 1;
        if (c < 2) {
            LOAD_X(c + 1);       // LDGs in flight under the MMAs
            CP_W(c + 1, db ^ 1); // async W copy under the MMAs
        }

        const uint32_t a_h = smb + db * 65536 + (mw * 64 + l15) * 128;
        const uint32_t a_l = a_h + 32768;
        uint32_t bb[2];
#pragma unroll
        for (int np = 0; np < 2; np++) {
            int oct = ((nw * 32 + np * 16) >> 3) + wo;
            bb[np] = smb + XBUF_B + db * 32768 + krl * 256 + ((oct ^ l7) << 4);
        }
#pragma unroll
        for (int ks = 0; ks < 4; ks++) {
            uint32_t Bh[2][4], Bl[2][4];
#pragma unroll
            for (int np = 0; np < 2; np++) {
                LDM4T(Bh[np], bb[np] + ks * 4096);
                LDM4T(Bl[np], bb[np] + ks * 4096 + 16384);
            }
            const uint32_t swA = (uint32_t)(((2 * ks + lk) ^ l7) << 4);
#pragma unroll
            for (int mt = 0; mt < 4; mt++) {
                uint32_t Ah[4], Al[4];
                LDM4(Ah, a_h + mt * 2048 + swA);
                LDM4(Al, a_l + mt * 2048 + swA);
                // term-major: dependent MMAs on each acc are 4 apart
#pragma unroll
                for (int nt = 0; nt < 4; nt++) {
                    const int np = nt >> 1, ix = nt & 1;
                    mma_bf16(acc[mt][nt], Ah, Bh[np][ix], Bh[np][2 + ix]);
                }
#pragma unroll
                for (int nt = 0; nt < 4; nt++) {
                    const int np = nt >> 1, ix = nt & 1;
                    mma_bf16(acc[mt][nt], Ah, Bl[np][ix], Bl[np][2 + ix]);
                }
#pragma unroll
                for (int nt = 0; nt < 4; nt++) {
                    const int np = nt >> 1, ix = nt & 1;
                    mma_bf16(acc[mt][nt], Al, Bh[np][ix], Bh[np][2 + ix]);
                }
            }
        }

        if (c < 2) {
            STS_X(db ^ 1);
            CPA_WAIT0();
            __syncthreads();
        }
    }
    __syncthreads();  // stage buffers reusable (gates alias them)

    // ---- epilogue: bias + activation -> gates smem [w][260]
    const bool isg = (mw == 3);
#pragma unroll
    for (int mt = 0; mt < 4; mt++) {
        const int m0 = mw * 64 + mt * 16;
        const float blo = bias[m0 + r];
        const float bhi = bias[m0 + 8 + r];
#pragma unroll
        for (int nt = 0; nt < 4; nt++) {
            const int w0 = nw * 32 + nt * 8 + 2 * cl;
            float v0 = acc[mt][nt][0] + blo;
            float v1 = acc[mt][nt][1] + blo;
            float v2 = acc[mt][nt][2] + bhi;
            float v3 = acc[mt][nt][3] + bhi;
            if (isg) { tanh2(v0, v1); tanh2(v2, v3); }
            else     { sigmoid2(v0, v1); sigmoid2(v2, v3); }
            smf[(size_t)w0 * GST + m0 + r]           = v0;
            smf[(size_t)(w0 + 1) * GST + m0 + r]     = v1;
            smf[(size_t)w0 * GST + m0 + 8 + r]       = v2;
            smf[(size_t)(w0 + 1) * GST + m0 + 8 + r] = v3;
        }
    }
    __syncthreads();

    // ---- LSTM scan: 8 segments of 16 w, parallel linear recurrence
    const int seg = tid >> 6;
    const int hc = tid & 63;
    {
        int gb = seg * 16 * GST + hc;
        float c = 0.0f, P = 1.0f;
#pragma unroll 8
        for (int j = 0; j < 16; j++) {
            float iv = smf[gb];
            float fv = smf[gb + 64];
            float gv = smf[gb + 192];
            c = fmaf(fv, c, iv * gv);
            P *= fv;
            smf[gb + 64] = c;
            smf[gb + 192] = P;
            gb += GST;
        }
        smf[PS_W + (seg * 64 + hc) * 2] = P;
        smf[PS_W + (seg * 64 + hc) * 2 + 1] = c;
    }
    __syncthreads();

    float cin = 0.0f;
#pragma unroll
    for (int s2 = 0; s2 < 7; s2++) {
        if (s2 < seg) {
            float P = smf[PS_W + (s2 * 64 + hc) * 2];
            float S = smf[PS_W + (s2 * 64 + hc) * 2 + 1];
            cin = fmaf(P, cin, S);
        }
    }

    {
        int gb = seg * 16 * GST + hc;
        float4* po = reinterpret_cast<float4*>(
            out + ((size_t)(b * HCv + hc) * Hv + h) * Wv + seg * 16);
        float hb[4];
#pragma unroll 2
        for (int j = 0; j < 16; j += 2) {
            float cp0 = smf[gb + 64],        fp0 = smf[gb + 192];
            float ov0 = smf[gb + 128];
            float cp1 = smf[gb + GST + 64],  fp1 = smf[gb + GST + 192];
            float ov1 = smf[gb + GST + 128];
            float t0 = fmaf(fp0, cin, cp0);
            float t1 = fmaf(fp1, cin, cp1);
            tanh2(t0, t1);
            hb[j & 3] = ov0 * t0;
            hb[(j & 3) + 1] = ov1 * t1;
            if ((j & 3) == 2)
                po[j >> 2] = make_float4(hb[0], hb[1], hb[2], hb[3]);
            gb += 2 * GST;
        }
    }
}

extern "C" void kernel_launch(void* const* d_in, const int* in_sizes, int n_in,
                              void* d_out, int out_size) {
    const float* x    = (const float*)d_in[0];
    const float* wgt  = (const float*)d_in[1];
    const float* bias = (const float*)d_in[2];
    float* out = (float*)d_out;

    cudaFuncSetAttribute(rowlstm_fused,
                         cudaFuncAttributeMaxDynamicSharedMemorySize, SMEM_BYTES);

    prep_w<<<192, 256>>>(wgt);
    rowlstm_fused<<<Bv * Hv, 512, SMEM_BYTES>>>(x, bias, out);
}

// round 6
// speedup vs baseline: 3.7889x; 1.3032x over previous
#include <cuda_runtime.h>
#include <cuda_fp16.h>
#include <cstdint>

#define Bv 16
#define Cv 64
#define Hv 128
#define Wv 128
#define HCv 64

// Pre-baked W image (single fp16 plane): [chunk(3)][m(256)][k(64) octet-swizzled]
__device__ __align__(16) uint16_t g_wimg[3 * 256 * 64];

// ---- smem map (bytes) ----
// WBUF: 2 x 32KB at 0 ; XBUF: 2 x 32KB (hi 16KB + lo 16KB) at 65536 -> 131072
// after mainloop (aliased): gates fp32 [w(128)][260 words] + PS at word 33280
#define XBUF_B   65536
#define GST      260
#define PS_W     33280
#define SMEM_BYTES 137216

extern __shared__ uint32_t smw[];

__device__ __forceinline__ uint32_t smem_u32(const void* p) {
    uint32_t a;
    asm("{ .reg .u64 t; cvta.to.shared.u64 t, %1; cvt.u32.u64 %0, t; }"
        : "=r"(a) : "l"(p));
    return a;
}

__device__ __forceinline__ float rcp_fast(float d) {
    float r;
    asm("rcp.approx.ftz.f32 %0, %1;" : "=f"(r) : "f"(d));
    return r;
}

// paired sigmoid: one RCP for two values
__device__ __forceinline__ void sigmoid2(float& v0, float& v1) {
    float e0 = __expf(-v0);
    float e1 = __expf(-v1);
    float p0 = 1.0f + e0, p1 = 1.0f + e1;
    float r = rcp_fast(p0 * p1);
    v0 = p1 * r;
    v1 = p0 * r;
}
// paired tanh: one RCP for two values
__device__ __forceinline__ void tanh2(float& v0, float& v1) {
    float e0 = __expf(-2.0f * fabsf(v0));
    float e1 = __expf(-2.0f * fabsf(v1));
    float p0 = 1.0f + e0, p1 = 1.0f + e1;
    float r = rcp_fast(p0 * p1);
    float t0 = (1.0f - e0) * p1 * r;
    float t1 = (1.0f - e1) * p0 * r;
    v0 = (v0 < 0.0f) ? -t0 : t0;
    v1 = (v1 < 0.0f) ? -t1 : t1;
}

__device__ __forceinline__ void mma_f16(float* c, const uint32_t* a,
                                        uint32_t b0, uint32_t b1) {
    asm volatile(
        "mma.sync.aligned.m16n8k16.row.col.f32.f16.f16.f32 "
        "{%0,%1,%2,%3}, {%4,%5,%6,%7}, {%8,%9}, {%0,%1,%2,%3};\n"
        : "+f"(c[0]), "+f"(c[1]), "+f"(c[2]), "+f"(c[3])
        : "r"(a[0]), "r"(a[1]), "r"(a[2]), "r"(a[3]), "r"(b0), "r"(b1));
}

#define LDM4(R, addr) \
    asm volatile("ldmatrix.sync.aligned.m8n8.x4.shared.b16 {%0,%1,%2,%3}, [%4];" \
        : "=r"((R)[0]), "=r"((R)[1]), "=r"((R)[2]), "=r"((R)[3]) : "r"(addr))
#define LDM4T(R, addr) \
    asm volatile("ldmatrix.sync.aligned.m8n8.x4.trans.shared.b16 {%0,%1,%2,%3}, [%4];" \
        : "=r"((R)[0]), "=r"((R)[1]), "=r"((R)[2]), "=r"((R)[3]) : "r"(addr))
#define CPA16(dst, src) \
    asm volatile("cp.async.ca.shared.global [%0], [%1], 16;" :: "r"(dst), "l"(src))
#define CPA_COMMIT() asm volatile("cp.async.commit_group;" ::: "memory")
#define CPA_WAIT0()  asm volatile("cp.async.wait_group 0;" ::: "memory")

// split v0,v1 into fp16 hi and fp16 lo (residual), pack as half2 words
__device__ __forceinline__ void split_pack_h(float v0, float v1,
                                             uint32_t& hi, uint32_t& lo) {
    __half h0 = __float2half_rn(v0);
    __half h1 = __float2half_rn(v1);
    __half l0 = __float2half_rn(v0 - __half2float(h0));
    __half l1 = __float2half_rn(v1 - __half2float(h1));
    hi = ((uint32_t)__half_as_ushort(h1) << 16) | __half_as_ushort(h0);
    lo = ((uint32_t)__half_as_ushort(l1) << 16) | __half_as_ushort(l0);
}

// ---------------------------------------------------------------- prep W image
// grid 192 (k), block 256 (m). Single fp16 plane, octet swizzle o^(m&7).
__global__ void prep_w(const float* __restrict__ wgt) {
    int k = blockIdx.x;
    int m = threadIdx.x;
    float v = wgt[m * 192 + k];
    int c = k >> 6, kl = k & 63, o = kl >> 3, e = kl & 7;
    g_wimg[c * 16384 + m * 64 + (((o ^ (m & 7)) << 3) + e)] =
        __half_as_ushort(__float2half_rn(v));
}

// ---------------------------------------------------------------- fused kernel
// One block per (b,h), 512 threads = 16 warps (4m x 4n), warp tile 64x32.
// 3 K-chunks of 64; cp.async double-buffered W (fp16), reg-prefetched X split fp16.
__global__ void __launch_bounds__(512, 1)
rowlstm_fused(const float* __restrict__ x, const float* __restrict__ bias,
              float* __restrict__ out) {
    float* smf = reinterpret_cast<float*>(smw);
    const int tid = threadIdx.x;
    const int lane = tid & 31;
    const int wid = tid >> 5;
    const int mw = wid & 3;
    const int nw = wid >> 2;
    const int r = lane >> 2, cl = lane & 3;
    const int bh = blockIdx.x, b = bh >> 7, h = bh & 127;

    const uint32_t smb = smem_u32(smw);

    // staging mapping
    const int woct = tid & 15;
    const int krbase = tid >> 4;   // 0..31

    // ldmatrix lane params
    const int l7 = lane & 7, l15 = lane & 15, lk = lane >> 4;
    const int krl = l7 + ((lane & 16) >> 1);
    const int wo = (lane >> 3) & 1;

    uint64_t gw;
    {
        const char* p = reinterpret_cast<const char*>(g_wimg);
        asm("cvta.to.global.u64 %0, %1;" : "=l"(gw) : "l"(p));
    }

    float acc[4][4][4];
#pragma unroll
    for (int mt = 0; mt < 4; mt++)
#pragma unroll
        for (int nt = 0; nt < 4; nt++)
#pragma unroll
            for (int q = 0; q < 4; q++) acc[mt][nt][q] = 0.0f;

    float4 pva[2], pvb[2];

#define LOAD_X(cn)                                                          \
    do {                                                                    \
        _Pragma("unroll") for (int j = 0; j < 2; j++) {                     \
            int krow = krbase + j * 32;                                     \
            int kg = (cn) * 64 + krow;                                      \
            int ic = kg / 3;                                                \
            int kh = kg - 3 * ic;                                           \
            int hp = h + kh - 2;                                            \
            if (hp >= 0) {                                                  \
                const float4* p4 = reinterpret_cast<const float4*>(         \
                    x + ((size_t)((b * Cv + ic) * Hv + hp)) * Wv + woct * 8); \
                pva[j] = p4[0];                                             \
                pvb[j] = p4[1];                                             \
            } else {                                                        \
                pva[j] = make_float4(0.f, 0.f, 0.f, 0.f);                   \
                pvb[j] = pva[j];                                            \
            }                                                               \
        }                                                                   \
    } while (0)

#define STS_X(db)                                                           \
    do {                                                                    \
        _Pragma("unroll") for (int j = 0; j < 2; j++) {                     \
            int krow = krbase + j * 32;                                     \
            uint32_t hiw[4], low[4];                                        \
            split_pack_h(pva[j].x, pva[j].y, hiw[0], low[0]);               \
            split_pack_h(pva[j].z, pva[j].w, hiw[1], low[1]);               \
            split_pack_h(pvb[j].x, pvb[j].y, hiw[2], low[2]);               \
            split_pack_h(pvb[j].z, pvb[j].w, hiw[3], low[3]);               \
            uint32_t a0 = smb + XBUF_B + (db) * 32768 + krow * 256 +        \
                          ((woct ^ (krow & 7)) << 4);                       \
            asm volatile("st.shared.v4.b32 [%0], {%1,%2,%3,%4};"            \
                         :: "r"(a0), "r"(hiw[0]), "r"(hiw[1]), "r"(hiw[2]), \
                            "r"(hiw[3]) : "memory");                        \
            asm volatile("st.shared.v4.b32 [%0], {%1,%2,%3,%4};"            \
                         :: "r"(a0 + 16384), "r"(low[0]), "r"(low[1]),      \
                            "r"(low[2]), "r"(low[3]) : "memory");           \
        }                                                                   \
    } while (0)

#define CP_W(cn, db)                                                        \
    do {                                                                    \
        uint64_t src = gw + (uint64_t)(cn) * 32768 + tid * 16;              \
        uint32_t dst = smb + (db) * 32768 + tid * 16;                       \
        _Pragma("unroll") for (int j = 0; j < 4; j++)                       \
            CPA16(dst + j * 8192, src + j * 8192);                          \
        CPA_COMMIT();                                                       \
    } while (0)

    // ---- preamble: stage chunk 0
    LOAD_X(0);
    CP_W(0, 0);
    STS_X(0);
    CPA_WAIT0();
    __syncthreads();

#pragma unroll
    for (int c = 0; c < 3; c++) {
        const int db = c & 1;
        if (c < 2) {
            LOAD_X(c + 1);       // LDGs in flight under the MMAs
            CP_W(c + 1, db ^ 1); // async W copy under the MMAs
        }

        const uint32_t a_h = smb + db * 32768 + (mw * 64 + l15) * 128;
        uint32_t bb[2];
#pragma unroll
        for (int np = 0; np < 2; np++) {
            int oct = ((nw * 32 + np * 16) >> 3) + wo;
            bb[np] = smb + XBUF_B + db * 32768 + krl * 256 + ((oct ^ l7) << 4);
        }
#pragma unroll
        for (int ks = 0; ks < 4; ks++) {
            uint32_t Bh[2][4], Bl[2][4];
#pragma unroll
            for (int np = 0; np < 2; np++) {
                LDM4T(Bh[np], bb[np] + ks * 4096);
                LDM4T(Bl[np], bb[np] + ks * 4096 + 16384);
            }
            const uint32_t swA = (uint32_t)(((2 * ks + lk) ^ l7) << 4);
#pragma unroll
            for (int mt = 0; mt < 4; mt++) {
                uint32_t A[4];
                LDM4(A, a_h + mt * 2048 + swA);
                // term-major: dependent MMAs on each acc are 4 apart
#pragma unroll
                for (int nt = 0; nt < 4; nt++) {
                    const int np = nt >> 1, ix = nt & 1;
                    mma_f16(acc[mt][nt], A, Bh[np][ix], Bh[np][2 + ix]);
                }
#pragma unroll
                for (int nt = 0; nt < 4; nt++) {
                    const int np = nt >> 1, ix = nt & 1;
                    mma_f16(acc[mt][nt], A, Bl[np][ix], Bl[np][2 + ix]);
                }
            }
        }

        if (c < 2) {
            STS_X(db ^ 1);
            CPA_WAIT0();
            __syncthreads();
        }
    }
    __syncthreads();  // stage buffers reusable (gates alias them)

    // ---- epilogue: bias + activation -> gates smem [w][260]
    const bool isg = (mw == 3);
#pragma unroll
    for (int mt = 0; mt < 4; mt++) {
        const int m0 = mw * 64 + mt * 16;
        const float blo = bias[m0 + r];
        const float bhi = bias[m0 + 8 + r];
#pragma unroll
        for (int nt = 0; nt < 4; nt++) {
            const int w0 = nw * 32 + nt * 8 + 2 * cl;
            float v0 = acc[mt][nt][0] + blo;
            float v1 = acc[mt][nt][1] + blo;
            float v2 = acc[mt][nt][2] + bhi;
            float v3 = acc[mt][nt][3] + bhi;
            if (isg) { tanh2(v0, v1); tanh2(v2, v3); }
            else     { sigmoid2(v0, v1); sigmoid2(v2, v3); }
            smf[(size_t)w0 * GST + m0 + r]           = v0;
            smf[(size_t)(w0 + 1) * GST + m0 + r]     = v1;
            smf[(size_t)w0 * GST + m0 + 8 + r]       = v2;
            smf[(size_t)(w0 + 1) * GST + m0 + 8 + r] = v3;
        }
    }
    __syncthreads();

    // ---- LSTM scan: 8 segments of 16 w, parallel linear recurrence
    const int seg = tid >> 6;
    const int hc = tid & 63;
    {
        int gb = seg * 16 * GST + hc;
        float c = 0.0f, P = 1.0f;
#pragma unroll 8
        for (int j = 0; j < 16; j++) {
            float iv = smf[gb];
            float fv = smf[gb + 64];
            float gv = smf[gb + 192];
            c = fmaf(fv, c, iv * gv);
            P *= fv;
            smf[gb + 64] = c;
            smf[gb + 192] = P;
            gb += GST;
        }
        smf[PS_W + (seg * 64 + hc) * 2] = P;
        smf[PS_W + (seg * 64 + hc) * 2 + 1] = c;
    }
    __syncthreads();

    float cin = 0.0f;
#pragma unroll
    for (int s2 = 0; s2 < 7; s2++) {
        if (s2 < seg) {
            float P = smf[PS_W + (s2 * 64 + hc) * 2];
            float S = smf[PS_W + (s2 * 64 + hc) * 2 + 1];
            cin = fmaf(P, cin, S);
        }
    }

    {
        int gb = seg * 16 * GST + hc;
        float4* po = reinterpret_cast<float4*>(
            out + ((size_t)(b * HCv + hc) * Hv + h) * Wv + seg * 16);
        float hb[4];
#pragma unroll 2
        for (int j = 0; j < 16; j += 2) {
            float cp0 = smf[gb + 64],        fp0 = smf[gb + 192];
            float ov0 = smf[gb + 128];
            float cp1 = smf[gb + GST + 64],  fp1 = smf[gb + GST + 192];
            float ov1 = smf[gb + GST + 128];
            float t0 = fmaf(fp0, cin, cp0);
            float t1 = fmaf(fp1, cin, cp1);
            tanh2(t0, t1);
            hb[j & 3] = ov0 * t0;
            hb[(j & 3) + 1] = ov1 * t1;
            if ((j & 3) == 2)
                po[j >> 2] = make_float4(hb[0], hb[1], hb[2], hb[3]);
            gb += 2 * GST;
        }
    }
}

extern "C" void kernel_launch(void* const* d_in, const int* in_sizes, int n_in,
                              void* d_out, int out_size) {
    const float* x    = (const float*)d_in[0];
    const float* wgt  = (const float*)d_in[1];
    const float* bias = (const float*)d_in[2];
    float* out = (float*)d_out;

    cudaFuncSetAttribute(rowlstm_fused,
                         cudaFuncAttributeMaxDynamicSharedMemorySize, SMEM_BYTES);

    prep_w<<<192, 256>>>(wgt);
    rowlstm_fused<<<Bv * Hv, 512, SMEM_BYTES>>>(x, bias, out);
}